// round 2
// baseline (speedup 1.0000x reference)
#include <cuda_runtime.h>

#define B_ 8
#define H_ 8
#define S_ 512
#define D_ 64
#define E_ 512

typedef unsigned long long ull;

// ---- packed f32x2 helpers (sm_103a full-rate fp32 path) ----
__device__ __forceinline__ ull pack_dup(float a) {
    ull r; asm("mov.b64 %0, {%1, %1};" : "=l"(r) : "f"(a)); return r;
}
__device__ __forceinline__ ull pack2(float x, float y) {
    ull r; asm("mov.b64 %0, {%1, %2};" : "=l"(r) : "f"(x), "f"(y)); return r;
}
__device__ __forceinline__ ull ffma2(ull a, ull b, ull c) {
    ull d; asm("fma.rn.f32x2 %0, %1, %2, %3;" : "=l"(d) : "l"(a), "l"(b), "l"(c)); return d;
}
__device__ __forceinline__ ull fadd2(ull a, ull b) {
    ull d; asm("add.rn.f32x2 %0, %1, %2;" : "=l"(d) : "l"(a), "l"(b)); return d;
}
__device__ __forceinline__ float2 unpack2(ull u) {
    float lo, hi; asm("mov.b64 {%0, %1}, %2;" : "=f"(lo), "=f"(hi) : "l"(u));
    float2 f; f.x = lo; f.y = hi; return f;
}

// ---- scratch (device globals; no runtime allocation allowed) ----
__device__ float g_Q[B_ * H_ * S_ * D_];             // [b][h][s][d]
__device__ float g_K[B_ * H_ * S_ * D_];             // [b][h][s][d], pre-scaled by 1/sqrt(D)
__device__ float g_V[B_ * H_ * S_ * D_];             // [b][h][s][d]
__device__ float g_P[(size_t)B_ * H_ * S_ * S_];     // softmax probs [b][h][i][j]  (67 MB)
__device__ float g_AO[B_ * S_ * E_];                 // attention out [b][s][h*64+d]

// ============================================================================
// proj_kernel: Y = X @ W^T + bias  (M=4096, N=512, K=512)
//   out_sel 0/1/2: write permuted [b][h][s][d] into g_Q/g_K/g_V, scaled
//   out_sel 3    : write plain [M][N] to Oext (final output)
//   in_sel  0    : X = Xext;  1: X = g_AO
// 64x64 tile, TK=16, 256 threads, 4x4 micro-tile, f32x2 inner product.
// ============================================================================
__global__ __launch_bounds__(256) void proj_kernel(
    const float* __restrict__ Xext, const float* __restrict__ W,
    const float* __restrict__ bias, float scale,
    int in_sel, int out_sel, float* __restrict__ Oext)
{
    const float* X = in_sel ? g_AO : Xext;
    float* out;
    if (out_sel == 0) out = g_Q;
    else if (out_sel == 1) out = g_K;
    else if (out_sel == 2) out = g_V;
    else out = Oext;

    __shared__ float Xs[16][68];   // [k][m], padded
    __shared__ float Ws[16][68];   // [k][n], padded

    const int m0 = blockIdx.x * 64;
    const int n0 = blockIdx.y * 64;
    const int tid = threadIdx.x;
    const int tx = tid & 15;        // n micro index
    const int ty = tid >> 4;        // m micro index
    const int lr = tid >> 2;        // load row 0..63
    const int lc = (tid & 3) * 4;   // load col 0,4,8,12

    ull acc[4][2];
#pragma unroll
    for (int i = 0; i < 4; i++) { acc[i][0] = 0ull; acc[i][1] = 0ull; }

    for (int k0 = 0; k0 < E_; k0 += 16) {
        float4 xa = *(const float4*)&X[(size_t)(m0 + lr) * E_ + k0 + lc];
        float4 wa = *(const float4*)&W[(size_t)(n0 + lr) * E_ + k0 + lc];
        __syncthreads();
        Xs[lc + 0][lr] = xa.x; Xs[lc + 1][lr] = xa.y;
        Xs[lc + 2][lr] = xa.z; Xs[lc + 3][lr] = xa.w;
        Ws[lc + 0][lr] = wa.x; Ws[lc + 1][lr] = wa.y;
        Ws[lc + 2][lr] = wa.z; Ws[lc + 3][lr] = wa.w;
        __syncthreads();
#pragma unroll
        for (int kk = 0; kk < 16; kk++) {
            float4 a4 = *(const float4*)&Xs[kk][ty * 4];
            float4 b4 = *(const float4*)&Ws[kk][tx * 4];
            ull bl = pack2(b4.x, b4.y);
            ull bh = pack2(b4.z, b4.w);
            ull a0 = pack_dup(a4.x), a1 = pack_dup(a4.y);
            ull a2 = pack_dup(a4.z), a3 = pack_dup(a4.w);
            acc[0][0] = ffma2(a0, bl, acc[0][0]); acc[0][1] = ffma2(a0, bh, acc[0][1]);
            acc[1][0] = ffma2(a1, bl, acc[1][0]); acc[1][1] = ffma2(a1, bh, acc[1][1]);
            acc[2][0] = ffma2(a2, bl, acc[2][0]); acc[2][1] = ffma2(a2, bh, acc[2][1]);
            acc[3][0] = ffma2(a3, bl, acc[3][0]); acc[3][1] = ffma2(a3, bh, acc[3][1]);
        }
    }

#pragma unroll
    for (int i = 0; i < 4; i++) {
        int m = m0 + ty * 4 + i;
        float2 c0 = unpack2(acc[i][0]);
        float2 c1 = unpack2(acc[i][1]);
        float vals[4] = {c0.x, c0.y, c1.x, c1.y};
#pragma unroll
        for (int j = 0; j < 4; j++) {
            int n = n0 + tx * 4 + j;
            float v = (vals[j] + bias[n]) * scale;
            if (out_sel < 3) {
                int bb = m >> 9;       // m / S_
                int s  = m & (S_ - 1);
                int hh = n >> 6;       // n / D_
                int dd = n & 63;
                out[((((size_t)bb * H_ + hh) * S_) + s) * D_ + dd] = v;
            } else {
                out[(size_t)m * E_ + n] = v;
            }
        }
    }
}

// ============================================================================
// attn_scores_kernel: per block (h, 4 rows of i), ALL 8 batches (warp==batch).
// scores[b,h,i,j] = q . (k_scaled + rel[i,j,h,:]) ; mask; row softmax -> g_P.
// rel is read once per block and shared logically across batches (L1 reuse),
// amortizing the 537 MB stream over the batch dimension.
// ============================================================================
__global__ __launch_bounds__(256) void attn_scores_kernel(
    const unsigned char* __restrict__ mask,
    const float* __restrict__ rel)
{
    const int h  = blockIdx.y;
    const int i0 = blockIdx.x * 4;
    const int tid  = threadIdx.x;
    const int b    = tid >> 5;
    const int lane = tid & 31;

    __shared__ float q_s[B_][4][D_];   // 8 KB
    for (int idx = tid; idx < B_ * 4 * D_; idx += 256) {
        int bb = idx >> 8;              // / 256
        int r  = idx & 255;
        int ii = r >> 6;
        int dd = r & 63;
        q_s[bb][ii][dd] = g_Q[((((size_t)bb * H_ + h) * S_) + i0 + ii) * D_ + dd];
    }
    __syncthreads();

    float acc[4][16];

    const float4* kbase = (const float4*)(g_K + (((size_t)b * H_ + h) * S_) * D_);
    const float4* qp = (const float4*)&q_s[b][0][0];
    const size_t REL_I_STRIDE4 = (size_t)S_ * H_ * D_ / 4;   // float4 stride per i

#pragma unroll 1
    for (int ji = 0; ji < 16; ji++) {
        int j = ji * 32 + lane;
        const float4* kp = kbase + (size_t)j * (D_ / 4);
        const float4* rp = (const float4*)(rel + ((((size_t)i0 * S_ + j) * H_) + h) * D_);

        ull p[4][2];
#pragma unroll
        for (int i = 0; i < 4; i++) { p[i][0] = 0ull; p[i][1] = 0ull; }

#pragma unroll
        for (int c = 0; c < 16; c++) {
            float4 k4 = kp[c];
            ull kl = pack2(k4.x, k4.y);
            ull kh = pack2(k4.z, k4.w);
#pragma unroll
            for (int i = 0; i < 4; i++) {
                float4 r4 = rp[(size_t)i * REL_I_STRIDE4 + c];
                float4 q4 = qp[i * 16 + c];
                ull tl = fadd2(kl, pack2(r4.x, r4.y));
                ull th = fadd2(kh, pack2(r4.z, r4.w));
                p[i][0] = ffma2(pack2(q4.x, q4.y), tl, p[i][0]);
                p[i][1] = ffma2(pack2(q4.z, q4.w), th, p[i][1]);
            }
        }
#pragma unroll
        for (int i = 0; i < 4; i++) {
            float2 f0 = unpack2(p[i][0]);
            float2 f1 = unpack2(p[i][1]);
            acc[i][ji] = (f0.x + f0.y) + (f1.x + f1.y);
        }
    }

    // key padding mask (byte-read; all-zero buffer is safe for any dtype)
    const unsigned char* mrow = mask + (size_t)b * S_;
#pragma unroll
    for (int ji = 0; ji < 16; ji++) {
        if (mrow[ji * 32 + lane]) {
#pragma unroll
            for (int i = 0; i < 4; i++) acc[i][ji] = -1e9f;
        }
    }

    // per-row softmax (row = 512 elems across 32 lanes x 16 regs)
    float* prow = g_P + ((size_t)((b * H_ + h) * S_ + i0)) * S_;
#pragma unroll
    for (int i = 0; i < 4; i++) {
        float m = -1e30f;
#pragma unroll
        for (int ji = 0; ji < 16; ji++) m = fmaxf(m, acc[i][ji]);
#pragma unroll
        for (int off = 16; off; off >>= 1)
            m = fmaxf(m, __shfl_xor_sync(0xffffffffu, m, off));
        float ssum = 0.f;
#pragma unroll
        for (int ji = 0; ji < 16; ji++) {
            float e = __expf(acc[i][ji] - m);
            acc[i][ji] = e;
            ssum += e;
        }
#pragma unroll
        for (int off = 16; off; off >>= 1)
            ssum += __shfl_xor_sync(0xffffffffu, ssum, off);
        float inv = 1.0f / ssum;
#pragma unroll
        for (int ji = 0; ji < 16; ji++)
            prow[(size_t)i * S_ + ji * 32 + lane] = acc[i][ji] * inv;
    }
}

// ============================================================================
// av_kernel: per (b,h): Out[512x64] = P[512x512] @ V[512x64]
// 64x64 tile (full N), TK=16, 256 threads, 4x4 micro, f32x2.
// Writes g_AO in [b][s][h*64+d] so the final projection is a plain GEMM.
// ============================================================================
__global__ __launch_bounds__(256) void av_kernel()
{
    const int bh = blockIdx.y;           // 0..63
    const int i0 = blockIdx.x * 64;
    const float* P = g_P + (size_t)bh * S_ * S_;
    const float* V = g_V + (size_t)bh * S_ * D_;

    __shared__ float As[16][68];   // [k][m] (P transposed tile)
    __shared__ float Bs[16][68];   // [k][n] (V tile direct)

    const int tid = threadIdx.x;
    const int tx = tid & 15;
    const int ty = tid >> 4;
    const int lr = tid >> 2;        // A load row 0..63
    const int lc = (tid & 3) * 4;   // A load col
    const int vr = tid >> 4;        // B load row 0..15
    const int vc = (tid & 15) * 4;  // B load col

    ull acc[4][2];
#pragma unroll
    for (int i = 0; i < 4; i++) { acc[i][0] = 0ull; acc[i][1] = 0ull; }

    for (int k0 = 0; k0 < S_; k0 += 16) {
        float4 pa = *(const float4*)&P[(size_t)(i0 + lr) * S_ + k0 + lc];
        float4 va = *(const float4*)&V[(size_t)(k0 + vr) * D_ + vc];
        __syncthreads();
        As[lc + 0][lr] = pa.x; As[lc + 1][lr] = pa.y;
        As[lc + 2][lr] = pa.z; As[lc + 3][lr] = pa.w;
        *(float4*)&Bs[vr][vc] = va;
        __syncthreads();
#pragma unroll
        for (int kk = 0; kk < 16; kk++) {
            float4 a4 = *(const float4*)&As[kk][ty * 4];
            float4 b4 = *(const float4*)&Bs[kk][tx * 4];
            ull bl = pack2(b4.x, b4.y);
            ull bh2 = pack2(b4.z, b4.w);
            ull a0 = pack_dup(a4.x), a1 = pack_dup(a4.y);
            ull a2 = pack_dup(a4.z), a3 = pack_dup(a4.w);
            acc[0][0] = ffma2(a0, bl, acc[0][0]); acc[0][1] = ffma2(a0, bh2, acc[0][1]);
            acc[1][0] = ffma2(a1, bl, acc[1][0]); acc[1][1] = ffma2(a1, bh2, acc[1][1]);
            acc[2][0] = ffma2(a2, bl, acc[2][0]); acc[2][1] = ffma2(a2, bh2, acc[2][1]);
            acc[3][0] = ffma2(a3, bl, acc[3][0]); acc[3][1] = ffma2(a3, bh2, acc[3][1]);
        }
    }

    const int b = bh >> 3;
    const int h = bh & 7;
#pragma unroll
    for (int i = 0; i < 4; i++) {
        int m = i0 + ty * 4 + i;              // sequence position s
        float2 c0 = unpack2(acc[i][0]);
        float2 c1 = unpack2(acc[i][1]);
        float vals[4] = {c0.x, c0.y, c1.x, c1.y};
#pragma unroll
        for (int j = 0; j < 4; j++) {
            int n = tx * 4 + j;               // d in 0..63
            g_AO[((size_t)b * S_ + m) * E_ + h * 64 + n] = vals[j];
        }
    }
}

// ============================================================================
extern "C" void kernel_launch(void* const* d_in, const int* in_sizes, int n_in,
                              void* d_out, int out_size)
{
    const float* query = (const float*)d_in[0];
    const float* key   = (const float*)d_in[1];
    const float* value = (const float*)d_in[2];
    const unsigned char* mask = (const unsigned char*)d_in[3];
    const float* rel = (const float*)d_in[4];
    const float* Wq = (const float*)d_in[5];
    const float* bq = (const float*)d_in[6];
    const float* Wk = (const float*)d_in[7];
    const float* bk = (const float*)d_in[8];
    const float* Wv = (const float*)d_in[9];
    const float* bv = (const float*)d_in[10];
    const float* Wo = (const float*)d_in[11];
    const float* bo = (const float*)d_in[12];
    float* out = (float*)d_out;

    dim3 gproj(64, 8);   // 4096/64 m-tiles, 512/64 n-tiles
    proj_kernel<<<gproj, 256>>>(query, Wq, bq, 1.0f,    0, 0, nullptr);
    proj_kernel<<<gproj, 256>>>(key,   Wk, bk, 0.125f,  0, 1, nullptr);  // 1/sqrt(64)
    proj_kernel<<<gproj, 256>>>(value, Wv, bv, 1.0f,    0, 2, nullptr);

    attn_scores_kernel<<<dim3(S_ / 4, H_), 256>>>(mask, rel);

    av_kernel<<<dim3(S_ / 64, B_ * H_), 256>>>();

    proj_kernel<<<gproj, 256>>>(nullptr, Wo, bo, 1.0f,  1, 3, out);
}

// round 4
// speedup vs baseline: 4.7864x; 4.7864x over previous
#include <cuda_runtime.h>
#include <cstdint>

#define B_ 8
#define H_ 8
#define S_ 512
#define D_ 64
#define E_ 512

typedef unsigned long long ull;

// ---- packed f32x2 helpers (sm_103a full-rate fp32 path) ----
__device__ __forceinline__ ull pack_dup(float a) {
    ull r; asm("mov.b64 %0, {%1, %1};" : "=l"(r) : "f"(a)); return r;
}
__device__ __forceinline__ ull pack2(float x, float y) {
    ull r; asm("mov.b64 %0, {%1, %2};" : "=l"(r) : "f"(x), "f"(y)); return r;
}
__device__ __forceinline__ ull ffma2(ull a, ull b, ull c) {
    ull d; asm("fma.rn.f32x2 %0, %1, %2, %3;" : "=l"(d) : "l"(a), "l"(b), "l"(c)); return d;
}
__device__ __forceinline__ float2 unpack2(ull u) {
    float lo, hi; asm("mov.b64 {%0, %1}, %2;" : "=f"(lo), "=f"(hi) : "l"(u));
    float2 f; f.x = lo; f.y = hi; return f;
}
__device__ __forceinline__ void cp_async16(void* dst, const void* src) {
    uint32_t s = (uint32_t)__cvta_generic_to_shared(dst);
    asm volatile("cp.async.cg.shared.global [%0], [%1], 16;" :: "r"(s), "l"(src));
}
#define CP_COMMIT() asm volatile("cp.async.commit_group;")

// ---- scratch (device globals; no runtime allocation allowed) ----
__device__ float g_Q [B_ * H_ * S_ * D_];            // [b][h][s][d]
__device__ float g_Kt[B_ * H_ * D_ * S_];            // [b][h][d][s], pre-scaled 1/8
__device__ float g_V [B_ * H_ * S_ * D_];            // [b][h][s][d]
__device__ float g_P [(size_t)B_ * H_ * S_ * S_];    // scores -> probs
__device__ float g_AO[B_ * S_ * E_];                 // attn out [b][s][h*64+d]

// ============================================================================
// proj_kernel: Y = X @ W^T + bias  (M=4096, N=512, K=512)
// 128x64 tile, TK=16, 256 threads, 8x4 micro, f32x2.
//   out_sel 0: g_Q [b][h][s][d]   1: g_Kt [b][h][d][s]   2: g_V   3: Oext
// ============================================================================
__global__ __launch_bounds__(256) void proj_kernel(
    const float* __restrict__ Xext, const float* __restrict__ W,
    const float* __restrict__ bias, float scale,
    int in_sel, int out_sel, float* __restrict__ Oext)
{
    const float* X = in_sel ? g_AO : Xext;
    float* out;
    if (out_sel == 0) out = g_Q;
    else if (out_sel == 1) out = g_Kt;
    else if (out_sel == 2) out = g_V;
    else out = Oext;

    __shared__ float Xs[16][136];   // [k][m]
    __shared__ float Ws[16][68];    // [k][n]

    const int m0 = blockIdx.x * 128;
    const int n0 = blockIdx.y * 64;
    const int tid = threadIdx.x;
    const int tx = tid & 15;        // n micro (4 each)
    const int ty = tid >> 4;        // m micro (8 each)
    const int lr = tid >> 1;        // X load row 0..127
    const int lc = (tid & 1) * 8;   // X load col 0 or 8
    const int wr = tid >> 2;        // W load row 0..63
    const int wc = (tid & 3) * 4;   // W load col

    ull acc[8][2];
#pragma unroll
    for (int i = 0; i < 8; i++) { acc[i][0] = 0ull; acc[i][1] = 0ull; }

    for (int k0 = 0; k0 < E_; k0 += 16) {
        float4 xa = *(const float4*)&X[(size_t)(m0 + lr) * E_ + k0 + lc];
        float4 xb = *(const float4*)&X[(size_t)(m0 + lr) * E_ + k0 + lc + 4];
        float4 wa = *(const float4*)&W[(size_t)(n0 + wr) * E_ + k0 + wc];
        __syncthreads();
        Xs[lc + 0][lr] = xa.x; Xs[lc + 1][lr] = xa.y;
        Xs[lc + 2][lr] = xa.z; Xs[lc + 3][lr] = xa.w;
        Xs[lc + 4][lr] = xb.x; Xs[lc + 5][lr] = xb.y;
        Xs[lc + 6][lr] = xb.z; Xs[lc + 7][lr] = xb.w;
        Ws[wc + 0][wr] = wa.x; Ws[wc + 1][wr] = wa.y;
        Ws[wc + 2][wr] = wa.z; Ws[wc + 3][wr] = wa.w;
        __syncthreads();
#pragma unroll
        for (int kk = 0; kk < 16; kk++) {
            float4 a0 = *(const float4*)&Xs[kk][ty * 8];
            float4 a1 = *(const float4*)&Xs[kk][ty * 8 + 4];
            float4 b4 = *(const float4*)&Ws[kk][tx * 4];
            ull bl = pack2(b4.x, b4.y);
            ull bh = pack2(b4.z, b4.w);
            float av[8] = {a0.x, a0.y, a0.z, a0.w, a1.x, a1.y, a1.z, a1.w};
#pragma unroll
            for (int i = 0; i < 8; i++) {
                ull ad = pack_dup(av[i]);
                acc[i][0] = ffma2(ad, bl, acc[i][0]);
                acc[i][1] = ffma2(ad, bh, acc[i][1]);
            }
        }
    }

#pragma unroll
    for (int i = 0; i < 8; i++) {
        int m = m0 + ty * 8 + i;
        float2 c0 = unpack2(acc[i][0]);
        float2 c1 = unpack2(acc[i][1]);
        float vals[4] = {c0.x, c0.y, c1.x, c1.y};
#pragma unroll
        for (int j = 0; j < 4; j++) {
            int n = n0 + tx * 4 + j;
            float v = (vals[j] + bias[n]) * scale;
            if (out_sel == 3) {
                out[(size_t)m * E_ + n] = v;
            } else {
                int bb = m >> 9, s = m & (S_ - 1);
                int hh = n >> 6, dd = n & 63;
                if (out_sel == 1)
                    out[(((size_t)bb * H_ + hh) * D_ + dd) * S_ + s] = v;   // d-major
                else
                    out[(((size_t)bb * H_ + hh) * S_ + s) * D_ + dd] = v;
            }
        }
    }
}

// ============================================================================
// qk_kernel: per (b,h): P[512x512] = Q[512x64] @ Kt[64x512]  (Kt pre-scaled)
// 128x64 tile, K=64, 256 threads, 8x4 micro.
// ============================================================================
__global__ __launch_bounds__(256) void qk_kernel()
{
    const int bh = blockIdx.z;
    const int i0 = blockIdx.x * 128;
    const int j0 = blockIdx.y * 64;
    const float* Q  = g_Q  + (size_t)bh * S_ * D_;
    const float* Kt = g_Kt + (size_t)bh * D_ * S_;

    __shared__ float Xs[16][136];
    __shared__ float Ws[16][68];

    const int tid = threadIdx.x;
    const int tx = tid & 15, ty = tid >> 4;
    const int lr = tid >> 1, lc = (tid & 1) * 8;
    const int dr = tid >> 4, dc = (tid & 15) * 4;

    ull acc[8][2];
#pragma unroll
    for (int i = 0; i < 8; i++) { acc[i][0] = 0ull; acc[i][1] = 0ull; }

    for (int k0 = 0; k0 < D_; k0 += 16) {
        float4 xa = *(const float4*)&Q[(size_t)(i0 + lr) * D_ + k0 + lc];
        float4 xb = *(const float4*)&Q[(size_t)(i0 + lr) * D_ + k0 + lc + 4];
        float4 wa = *(const float4*)&Kt[(size_t)(k0 + dr) * S_ + j0 + dc];
        __syncthreads();
        Xs[lc + 0][lr] = xa.x; Xs[lc + 1][lr] = xa.y;
        Xs[lc + 2][lr] = xa.z; Xs[lc + 3][lr] = xa.w;
        Xs[lc + 4][lr] = xb.x; Xs[lc + 5][lr] = xb.y;
        Xs[lc + 6][lr] = xb.z; Xs[lc + 7][lr] = xb.w;
        *(float4*)&Ws[dr][dc] = wa;
        __syncthreads();
#pragma unroll
        for (int kk = 0; kk < 16; kk++) {
            float4 a0 = *(const float4*)&Xs[kk][ty * 8];
            float4 a1 = *(const float4*)&Xs[kk][ty * 8 + 4];
            float4 b4 = *(const float4*)&Ws[kk][tx * 4];
            ull bl = pack2(b4.x, b4.y);
            ull bh = pack2(b4.z, b4.w);
            float av[8] = {a0.x, a0.y, a0.z, a0.w, a1.x, a1.y, a1.z, a1.w};
#pragma unroll
            for (int i = 0; i < 8; i++) {
                ull ad = pack_dup(av[i]);
                acc[i][0] = ffma2(ad, bl, acc[i][0]);
                acc[i][1] = ffma2(ad, bh, acc[i][1]);
            }
        }
    }

    float* Pout = g_P + (size_t)bh * S_ * S_;
#pragma unroll
    for (int i = 0; i < 8; i++) {
        int m = i0 + ty * 8 + i;
        float2 c0 = unpack2(acc[i][0]);
        float2 c1 = unpack2(acc[i][1]);
        float vals[4] = {c0.x, c0.y, c1.x, c1.y};
#pragma unroll
        for (int j = 0; j < 4; j++)
            Pout[(size_t)m * S_ + j0 + tx * 4 + j] = vals[j];
    }
}

// ============================================================================
// relsoftmax_kernel: block = (h, i0..i0+3). Adds q.rel bias to qk scores,
// masks, softmaxes full rows, writes probs to g_P.
// rel staged gmem->smem COALESCED (lanes along d), cp.async double-buffered;
// compute reads smem with lane=j, warp owns (i, j-half), all 8 batches in regs.
// ============================================================================
#define ROWF 68                           // floats per (i,jh,jj) smem row (64+pad)
#define STG_F (4 * 2 * 32 * ROWF)         // 17408 floats per stage

__global__ __launch_bounds__(256, 1) void relsoftmax_kernel(
    const unsigned char* __restrict__ mask,
    const float* __restrict__ rel)
{
    extern __shared__ float sm[];
    float* stg0 = sm;
    float* stg1 = sm + STG_F;
    ull*   q_s  = (ull*)(sm + 2 * STG_F);          // [4i][8b][32d2]
    float* redm = sm + 2 * STG_F + 2048;           // [4i][8b][2jh]
    float* reds = redm + 64;

    const int h  = blockIdx.y;
    const int i0 = blockIdx.x * 4;
    const int tid  = threadIdx.x;
    const int w    = tid >> 5;
    const int lane = tid & 31;
    const int il = w >> 1;        // i within tile
    const int jh = w & 1;         // j half (0: j<256, 1: j>=256)

    // load Q tile as packed float2: q_s[(il*8+b)*32 + d2]
    for (int t = tid; t < 1024; t += 256) {
        int d2 = t & 31, b = (t >> 5) & 7, ii = t >> 8;
        q_s[t] = *(const ull*)&g_Q[(((size_t)(b * H_ + h) * S_) + i0 + ii) * D_ + d2 * 2];
    }

    ull acc[8][8];                 // [b][round]
#pragma unroll
    for (int b = 0; b < 8; b++)
#pragma unroll
        for (int r = 0; r < 8; r++) acc[b][r] = 0ull;

    // round r covers j in {jh*256 + r*32 + 0..31} for both halves, all 4 i
    auto load_round = [&](int r, float* buf) {
#pragma unroll
        for (int t = 0; t < 16; t++) {
            int f = tid + t * 256;
            int d4 = f & 15, jj = (f >> 4) & 31, jhh = (f >> 9) & 1, ii = f >> 10;
            int j = jhh * 256 + r * 32 + jj;
            const float* src = rel +
                ((((size_t)(i0 + ii) * S_ + j) * H_) + h) * D_ + d4 * 4;
            float* dst = buf + ((size_t)((ii * 2 + jhh) * 32 + jj)) * ROWF + d4 * 4;
            cp_async16(dst, src);
        }
        CP_COMMIT();
    };

    load_round(0, stg0);
#pragma unroll
    for (int r = 0; r < 8; r++) {
        float* curbuf = (r & 1) ? stg1 : stg0;
        if (r < 7) {
            load_round(r + 1, (r & 1) ? stg0 : stg1);
            asm volatile("cp.async.wait_group 1;");
        } else {
            asm volatile("cp.async.wait_group 0;");
        }
        __syncthreads();
        const float* relrow = curbuf + ((size_t)((il * 2 + jh) * 32 + lane)) * ROWF;
        const ull* qrow = q_s + il * 256;
#pragma unroll 4
        for (int d2 = 0; d2 < 32; d2++) {
            ull r2 = *(const ull*)(relrow + d2 * 2);
#pragma unroll
            for (int b = 0; b < 8; b++)
                acc[b][r] = ffma2(qrow[b * 32 + d2], r2, acc[b][r]);
        }
        __syncthreads();
    }

    // combine with qk scores, mask
    float sc[8][8];
#pragma unroll
    for (int b = 0; b < 8; b++) {
        const float* gp = g_P + (((size_t)(b * H_ + h) * S_) + i0 + il) * S_ + jh * 256 + lane;
        const unsigned char* mrow = mask + (size_t)b * S_ + jh * 256 + lane;
#pragma unroll
        for (int r = 0; r < 8; r++) {
            float2 f = unpack2(acc[b][r]);
            float s = f.x + f.y + gp[r * 32];
            if (mrow[r * 32]) s = -1e9f;
            sc[b][r] = s;
        }
    }

    // half-row max
#pragma unroll
    for (int b = 0; b < 8; b++) {
        float m = sc[b][0];
#pragma unroll
        for (int r = 1; r < 8; r++) m = fmaxf(m, sc[b][r]);
#pragma unroll
        for (int off = 16; off; off >>= 1)
            m = fmaxf(m, __shfl_xor_sync(0xffffffffu, m, off));
        if (lane == 0) redm[(il * 8 + b) * 2 + jh] = m;
    }
    __syncthreads();
#pragma unroll
    for (int b = 0; b < 8; b++) {
        float m = fmaxf(redm[(il * 8 + b) * 2], redm[(il * 8 + b) * 2 + 1]);
        float ssum = 0.f;
#pragma unroll
        for (int r = 0; r < 8; r++) {
            float e = __expf(sc[b][r] - m);
            sc[b][r] = e;
            ssum += e;
        }
#pragma unroll
        for (int off = 16; off; off >>= 1)
            ssum += __shfl_xor_sync(0xffffffffu, ssum, off);
        if (lane == 0) reds[(il * 8 + b) * 2 + jh] = ssum;
    }
    __syncthreads();
#pragma unroll
    for (int b = 0; b < 8; b++) {
        float inv = 1.0f / (reds[(il * 8 + b) * 2] + reds[(il * 8 + b) * 2 + 1]);
        float* gp = g_P + (((size_t)(b * H_ + h) * S_) + i0 + il) * S_ + jh * 256 + lane;
#pragma unroll
        for (int r = 0; r < 8; r++)
            gp[r * 32] = sc[b][r] * inv;
    }
}

// ============================================================================
// av_kernel: per (b,h): Out[512x64] = P[512x512] @ V[512x64]
// 128x64 tile, TK=16, 256 threads, 8x4 micro.
// ============================================================================
__global__ __launch_bounds__(256) void av_kernel()
{
    const int bh = blockIdx.y;
    const int i0 = blockIdx.x * 128;
    const float* P = g_P + (size_t)bh * S_ * S_;
    const float* V = g_V + (size_t)bh * S_ * D_;

    __shared__ float Xs[16][136];
    __shared__ float Ws[16][68];

    const int tid = threadIdx.x;
    const int tx = tid & 15, ty = tid >> 4;
    const int lr = tid >> 1, lc = (tid & 1) * 8;
    const int vr = tid >> 4, vc = (tid & 15) * 4;

    ull acc[8][2];
#pragma unroll
    for (int i = 0; i < 8; i++) { acc[i][0] = 0ull; acc[i][1] = 0ull; }

    for (int k0 = 0; k0 < S_; k0 += 16) {
        float4 xa = *(const float4*)&P[(size_t)(i0 + lr) * S_ + k0 + lc];
        float4 xb = *(const float4*)&P[(size_t)(i0 + lr) * S_ + k0 + lc + 4];
        float4 wa = *(const float4*)&V[(size_t)(k0 + vr) * D_ + vc];
        __syncthreads();
        Xs[lc + 0][lr] = xa.x; Xs[lc + 1][lr] = xa.y;
        Xs[lc + 2][lr] = xa.z; Xs[lc + 3][lr] = xa.w;
        Xs[lc + 4][lr] = xb.x; Xs[lc + 5][lr] = xb.y;
        Xs[lc + 6][lr] = xb.z; Xs[lc + 7][lr] = xb.w;
        *(float4*)&Ws[vr][vc] = wa;
        __syncthreads();
#pragma unroll
        for (int kk = 0; kk < 16; kk++) {
            float4 a0 = *(const float4*)&Xs[kk][ty * 8];
            float4 a1 = *(const float4*)&Xs[kk][ty * 8 + 4];
            float4 b4 = *(const float4*)&Ws[kk][tx * 4];
            ull bl = pack2(b4.x, b4.y);
            ull bh2 = pack2(b4.z, b4.w);
            float av[8] = {a0.x, a0.y, a0.z, a0.w, a1.x, a1.y, a1.z, a1.w};
#pragma unroll
            for (int i = 0; i < 8; i++) {
                ull ad = pack_dup(av[i]);
                acc[i][0] = ffma2(ad, bl, acc[i][0]);
                acc[i][1] = ffma2(ad, bh2, acc[i][1]);
            }
        }
    }

    const int b = bh >> 3, h = bh & 7;
#pragma unroll
    for (int i = 0; i < 8; i++) {
        int m = i0 + ty * 8 + i;
        float2 c0 = unpack2(acc[i][0]);
        float2 c1 = unpack2(acc[i][1]);
        float vals[4] = {c0.x, c0.y, c1.x, c1.y};
#pragma unroll
        for (int j = 0; j < 4; j++) {
            int n = tx * 4 + j;
            g_AO[((size_t)b * S_ + m) * E_ + h * 64 + n] = vals[j];
        }
    }
}

// ============================================================================
extern "C" void kernel_launch(void* const* d_in, const int* in_sizes, int n_in,
                              void* d_out, int out_size)
{
    const float* query = (const float*)d_in[0];
    const float* key   = (const float*)d_in[1];
    const float* value = (const float*)d_in[2];
    const unsigned char* mask = (const unsigned char*)d_in[3];
    const float* rel = (const float*)d_in[4];
    const float* Wq = (const float*)d_in[5];
    const float* bq = (const float*)d_in[6];
    const float* Wk = (const float*)d_in[7];
    const float* bk = (const float*)d_in[8];
    const float* Wv = (const float*)d_in[9];
    const float* bv = (const float*)d_in[10];
    const float* Wo = (const float*)d_in[11];
    const float* bo = (const float*)d_in[12];
    float* out = (float*)d_out;

    const int RS_SMEM = (2 * STG_F + 2048 + 128) * 4;   // ~148 KB
    cudaFuncSetAttribute(relsoftmax_kernel,
                         cudaFuncAttributeMaxDynamicSharedMemorySize, RS_SMEM);

    dim3 gproj(32, 8);   // 4096/128 m-tiles, 512/64 n-tiles
    proj_kernel<<<gproj, 256>>>(query, Wq, bq, 1.0f,   0, 0, nullptr);
    proj_kernel<<<gproj, 256>>>(key,   Wk, bk, 0.125f, 0, 1, nullptr);  // K^T, pre-scaled
    proj_kernel<<<gproj, 256>>>(value, Wv, bv, 1.0f,   0, 2, nullptr);

    qk_kernel<<<dim3(4, 8, 64), 256>>>();

    relsoftmax_kernel<<<dim3(S_ / 4, H_), 256, RS_SMEM>>>(mask, rel);

    av_kernel<<<dim3(4, 64), 256>>>();

    proj_kernel<<<gproj, 256>>>(nullptr, Wo, bo, 1.0f, 1, 3, out);
}

// round 8
// speedup vs baseline: 5.1318x; 1.0722x over previous
#include <cuda_runtime.h>
#include <cstdint>

#define B_ 8
#define H_ 8
#define S_ 512
#define D_ 64
#define E_ 512

typedef unsigned long long ull;

// ---- packed f32x2 helpers ----
__device__ __forceinline__ ull pack_dup(float a) {
    ull r; asm("mov.b64 %0, {%1, %1};" : "=l"(r) : "f"(a)); return r;
}
__device__ __forceinline__ ull pack2(float x, float y) {
    ull r; asm("mov.b64 %0, {%1, %2};" : "=l"(r) : "f"(x), "f"(y)); return r;
}
__device__ __forceinline__ ull ffma2(ull a, ull b, ull c) {
    ull d; asm("fma.rn.f32x2 %0, %1, %2, %3;" : "=l"(d) : "l"(a), "l"(b), "l"(c)); return d;
}
__device__ __forceinline__ float2 unpack2(ull u) {
    float lo, hi; asm("mov.b64 {%0, %1}, %2;" : "=f"(lo), "=f"(hi) : "l"(u));
    float2 f; f.x = lo; f.y = hi; return f;
}
__device__ __forceinline__ void cp_async16(void* dst, const void* src) {
    uint32_t s = (uint32_t)__cvta_generic_to_shared(dst);
    asm volatile("cp.async.cg.shared.global [%0], [%1], 16;" :: "r"(s), "l"(src));
}
#define CP_COMMIT() asm volatile("cp.async.commit_group;")

// ---- scratch ----
__device__ float g_Q [B_ * H_ * S_ * D_];
__device__ float g_Kt[B_ * H_ * D_ * S_];            // [b][h][d][s], pre-scaled 1/8
__device__ float g_V [B_ * H_ * S_ * D_];
__device__ float g_P [(size_t)B_ * H_ * S_ * S_];
__device__ float g_AO[B_ * S_ * E_];

#define PITCH 132   // smem pitch (floats): multiple of 4 for LDS.128 alignment

// 8x8 micro-tile inner step: 32 FFMA2 from 4 LDS.128
#define MICRO_KK(XS, WS)                                                    \
    {                                                                       \
        float4 a0 = *(const float4*)&XS[kk][ty * 8];                        \
        float4 a1 = *(const float4*)&XS[kk][ty * 8 + 4];                    \
        float4 b0 = *(const float4*)&WS[kk][tx * 8];                        \
        float4 b1 = *(const float4*)&WS[kk][tx * 8 + 4];                    \
        ull bp0 = pack2(b0.x, b0.y), bp1 = pack2(b0.z, b0.w);               \
        ull bp2 = pack2(b1.x, b1.y), bp3 = pack2(b1.z, b1.w);               \
        float av_[8] = {a0.x, a0.y, a0.z, a0.w, a1.x, a1.y, a1.z, a1.w};    \
        _Pragma("unroll")                                                   \
        for (int i = 0; i < 8; i++) {                                       \
            ull ad = pack_dup(av_[i]);                                      \
            acc[i][0] = ffma2(ad, bp0, acc[i][0]);                          \
            acc[i][1] = ffma2(ad, bp1, acc[i][1]);                          \
            acc[i][2] = ffma2(ad, bp2, acc[i][2]);                          \
            acc[i][3] = ffma2(ad, bp3, acc[i][3]);                          \
        }                                                                   \
    }

#define UNPACK_C()                                                          \
    float c[8][8];                                                          \
    _Pragma("unroll")                                                       \
    for (int i = 0; i < 8; i++)                                             \
        _Pragma("unroll")                                                   \
        for (int jp = 0; jp < 4; jp++) {                                    \
            float2 f = unpack2(acc[i][jp]);                                 \
            c[i][jp * 2] = f.x; c[i][jp * 2 + 1] = f.y;                     \
        }

// ============================================================================
// proj_kernel: Y = X @ W^T + bias  (M=4096, N=512, K=512)
// 128x128 tile, TK=16, 256 threads, 8x8 micro, reg-prefetch pipeline.
// ============================================================================
__global__ __launch_bounds__(256, 2) void proj_kernel(
    const float* __restrict__ Xext, const float* __restrict__ W,
    const float* __restrict__ bias, float scale,
    int in_sel, int out_sel, float* __restrict__ Oext)
{
    const float* X = in_sel ? g_AO : Xext;
    float* out;
    if (out_sel == 0) out = g_Q;
    else if (out_sel == 1) out = g_Kt;
    else if (out_sel == 2) out = g_V;
    else out = Oext;

    __shared__ float Xs[16][PITCH];
    __shared__ float Ws[16][PITCH];

    const int m0 = blockIdx.x * 128;
    const int n0 = blockIdx.y * 128;
    const int tid = threadIdx.x;
    const int tx = tid & 15, ty = tid >> 4;
    const int lr = tid >> 1, lc = (tid & 1) * 8;

    const float* Xrow = X + (size_t)(m0 + lr) * E_ + lc;
    const float* Wrow = W + (size_t)(n0 + lr) * E_ + lc;

    ull acc[8][4];
#pragma unroll
    for (int i = 0; i < 8; i++)
#pragma unroll
        for (int j = 0; j < 4; j++) acc[i][j] = 0ull;

    float4 x0 = *(const float4*)(Xrow);
    float4 x1 = *(const float4*)(Xrow + 4);
    float4 w0 = *(const float4*)(Wrow);
    float4 w1 = *(const float4*)(Wrow + 4);

    for (int k0 = 0; k0 < E_; k0 += 16) {
        Xs[lc + 0][lr] = x0.x; Xs[lc + 1][lr] = x0.y;
        Xs[lc + 2][lr] = x0.z; Xs[lc + 3][lr] = x0.w;
        Xs[lc + 4][lr] = x1.x; Xs[lc + 5][lr] = x1.y;
        Xs[lc + 6][lr] = x1.z; Xs[lc + 7][lr] = x1.w;
        Ws[lc + 0][lr] = w0.x; Ws[lc + 1][lr] = w0.y;
        Ws[lc + 2][lr] = w0.z; Ws[lc + 3][lr] = w0.w;
        Ws[lc + 4][lr] = w1.x; Ws[lc + 5][lr] = w1.y;
        Ws[lc + 6][lr] = w1.z; Ws[lc + 7][lr] = w1.w;
        __syncthreads();
        if (k0 + 16 < E_) {
            x0 = *(const float4*)(Xrow + k0 + 16);
            x1 = *(const float4*)(Xrow + k0 + 20);
            w0 = *(const float4*)(Wrow + k0 + 16);
            w1 = *(const float4*)(Wrow + k0 + 20);
        }
#pragma unroll
        for (int kk = 0; kk < 16; kk++) MICRO_KK(Xs, Ws)
        __syncthreads();
    }

    UNPACK_C()

    float bj[8];
#pragma unroll
    for (int j = 0; j < 8; j++) bj[j] = bias[n0 + tx * 8 + j];

    if (out_sel == 3) {
#pragma unroll
        for (int i = 0; i < 8; i++) {
            int m = m0 + ty * 8 + i;
            float4 v0 = {(c[i][0] + bj[0]), (c[i][1] + bj[1]),
                         (c[i][2] + bj[2]), (c[i][3] + bj[3])};
            float4 v1 = {(c[i][4] + bj[4]), (c[i][5] + bj[5]),
                         (c[i][6] + bj[6]), (c[i][7] + bj[7])};
            *(float4*)&out[(size_t)m * E_ + n0 + tx * 8]     = v0;
            *(float4*)&out[(size_t)m * E_ + n0 + tx * 8 + 4] = v1;
        }
    } else if (out_sel == 1) {
        // K^T d-major: column stores, vectorized along s
        const int bb = m0 >> 9;
        const int s0 = (m0 & (S_ - 1)) + ty * 8;
#pragma unroll
        for (int j = 0; j < 8; j++) {
            int n = n0 + tx * 8 + j;
            int hh = n >> 6, dd = n & 63;
            float* col = out + (((size_t)(bb * H_ + hh) * D_) + dd) * S_ + s0;
            float4 v0 = {(c[0][j] + bj[j]) * scale, (c[1][j] + bj[j]) * scale,
                         (c[2][j] + bj[j]) * scale, (c[3][j] + bj[j]) * scale};
            float4 v1 = {(c[4][j] + bj[j]) * scale, (c[5][j] + bj[j]) * scale,
                         (c[6][j] + bj[j]) * scale, (c[7][j] + bj[j]) * scale};
            *(float4*)col = v0;
            *(float4*)(col + 4) = v1;
        }
    } else {
        const int bb = m0 >> 9;
        const int hh = (n0 + tx * 8) >> 6;
        const int dd = (n0 + tx * 8) & 63;
#pragma unroll
        for (int i = 0; i < 8; i++) {
            int s = (m0 & (S_ - 1)) + ty * 8 + i;
            float* row = out + (((size_t)(bb * H_ + hh) * S_) + s) * D_ + dd;
            float4 v0 = {c[i][0] + bj[0], c[i][1] + bj[1],
                         c[i][2] + bj[2], c[i][3] + bj[3]};
            float4 v1 = {c[i][4] + bj[4], c[i][5] + bj[5],
                         c[i][6] + bj[6], c[i][7] + bj[7]};
            *(float4*)row = v0;
            *(float4*)(row + 4) = v1;
        }
    }
}

// ============================================================================
// qk_kernel: per (b,h): P[512x512] = Q[512x64] @ Kt[64x512]
// 128x128 tile, TK=16 (4 stages), 256 threads, 8x8 micro.
// Kt is already k-major in gmem -> direct float4 STS, no transpose.
// ============================================================================
__global__ __launch_bounds__(256, 2) void qk_kernel()
{
    const int bh = blockIdx.z;
    const int i0 = blockIdx.x * 128;
    const int j0 = blockIdx.y * 128;
    const float* Q  = g_Q  + (size_t)bh * S_ * D_;
    const float* Kt = g_Kt + (size_t)bh * D_ * S_;

    __shared__ float Xs[16][PITCH];
    __shared__ float Ws[16][PITCH];

    const int tid = threadIdx.x;
    const int tx = tid & 15, ty = tid >> 4;
    const int lr = tid >> 1, lc = (tid & 1) * 8;     // Q loads (transpose)
    const int kr = tid >> 4, kc = (tid & 15) * 8;    // Kt loads (direct)

    const float* Qrow  = Q + (size_t)(i0 + lr) * D_ + lc;
    const float* Ktrow = Kt + (size_t)kr * S_ + j0 + kc;

    ull acc[8][4];
#pragma unroll
    for (int i = 0; i < 8; i++)
#pragma unroll
        for (int j = 0; j < 4; j++) acc[i][j] = 0ull;

    float4 x0 = *(const float4*)(Qrow);
    float4 x1 = *(const float4*)(Qrow + 4);
    float4 w0 = *(const float4*)(Ktrow);
    float4 w1 = *(const float4*)(Ktrow + 4);

    for (int k0 = 0; k0 < D_; k0 += 16) {
        Xs[lc + 0][lr] = x0.x; Xs[lc + 1][lr] = x0.y;
        Xs[lc + 2][lr] = x0.z; Xs[lc + 3][lr] = x0.w;
        Xs[lc + 4][lr] = x1.x; Xs[lc + 5][lr] = x1.y;
        Xs[lc + 6][lr] = x1.z; Xs[lc + 7][lr] = x1.w;
        *(float4*)&Ws[kr][kc]     = w0;
        *(float4*)&Ws[kr][kc + 4] = w1;
        __syncthreads();
        if (k0 + 16 < D_) {
            x0 = *(const float4*)(Qrow + k0 + 16);
            x1 = *(const float4*)(Qrow + k0 + 20);
            w0 = *(const float4*)(Ktrow + (size_t)(k0 + 16) * S_);
            w1 = *(const float4*)(Ktrow + (size_t)(k0 + 16) * S_ + 4);
        }
#pragma unroll
        for (int kk = 0; kk < 16; kk++) MICRO_KK(Xs, Ws)
        __syncthreads();
    }

    UNPACK_C()

    float* Pout = g_P + (size_t)bh * S_ * S_;
#pragma unroll
    for (int i = 0; i < 8; i++) {
        int m = i0 + ty * 8 + i;
        float4 v0 = {c[i][0], c[i][1], c[i][2], c[i][3]};
        float4 v1 = {c[i][4], c[i][5], c[i][6], c[i][7]};
        *(float4*)&Pout[(size_t)m * S_ + j0 + tx * 8]     = v0;
        *(float4*)&Pout[(size_t)m * S_ + j0 + tx * 8 + 4] = v1;
    }
}

// ============================================================================
// relsoftmax_kernel (unchanged from R3): adds q.rel bias, masks, softmax.
// ============================================================================
#define ROWF 68
#define STG_F (4 * 2 * 32 * ROWF)

__global__ __launch_bounds__(256, 1) void relsoftmax_kernel(
    const unsigned char* __restrict__ mask,
    const float* __restrict__ rel)
{
    extern __shared__ float sm[];
    float* stg0 = sm;
    float* stg1 = sm + STG_F;
    ull*   q_s  = (ull*)(sm + 2 * STG_F);
    float* redm = sm + 2 * STG_F + 2048;
    float* reds = redm + 64;

    const int h  = blockIdx.y;
    const int i0 = blockIdx.x * 4;
    const int tid  = threadIdx.x;
    const int w    = tid >> 5;
    const int lane = tid & 31;
    const int il = w >> 1;
    const int jh = w & 1;

    for (int t = tid; t < 1024; t += 256) {
        int d2 = t & 31, b = (t >> 5) & 7, ii = t >> 8;
        q_s[t] = *(const ull*)&g_Q[(((size_t)(b * H_ + h) * S_) + i0 + ii) * D_ + d2 * 2];
    }

    ull acc[8][8];
#pragma unroll
    for (int b = 0; b < 8; b++)
#pragma unroll
        for (int r = 0; r < 8; r++) acc[b][r] = 0ull;

    auto load_round = [&](int r, float* buf) {
#pragma unroll
        for (int t = 0; t < 16; t++) {
            int f = tid + t * 256;
            int d4 = f & 15, jj = (f >> 4) & 31, jhh = (f >> 9) & 1, ii = f >> 10;
            int j = jhh * 256 + r * 32 + jj;
            const float* src = rel +
                ((((size_t)(i0 + ii) * S_ + j) * H_) + h) * D_ + d4 * 4;
            float* dst = buf + ((size_t)((ii * 2 + jhh) * 32 + jj)) * ROWF + d4 * 4;
            cp_async16(dst, src);
        }
        CP_COMMIT();
    };

    load_round(0, stg0);
#pragma unroll
    for (int r = 0; r < 8; r++) {
        float* curbuf = (r & 1) ? stg1 : stg0;
        if (r < 7) {
            load_round(r + 1, (r & 1) ? stg0 : stg1);
            asm volatile("cp.async.wait_group 1;");
        } else {
            asm volatile("cp.async.wait_group 0;");
        }
        __syncthreads();
        const float* relrow = curbuf + ((size_t)((il * 2 + jh) * 32 + lane)) * ROWF;
        const ull* qrow = q_s + il * 256;
#pragma unroll 4
        for (int d2 = 0; d2 < 32; d2++) {
            ull r2 = *(const ull*)(relrow + d2 * 2);
#pragma unroll
            for (int b = 0; b < 8; b++)
                acc[b][r] = ffma2(qrow[b * 32 + d2], r2, acc[b][r]);
        }
        __syncthreads();
    }

    float sc[8][8];
#pragma unroll
    for (int b = 0; b < 8; b++) {
        const float* gp = g_P + (((size_t)(b * H_ + h) * S_) + i0 + il) * S_ + jh * 256 + lane;
        const unsigned char* mrow = mask + (size_t)b * S_ + jh * 256 + lane;
#pragma unroll
        for (int r = 0; r < 8; r++) {
            float2 f = unpack2(acc[b][r]);
            float s = f.x + f.y + gp[r * 32];
            if (mrow[r * 32]) s = -1e9f;
            sc[b][r] = s;
        }
    }

#pragma unroll
    for (int b = 0; b < 8; b++) {
        float m = sc[b][0];
#pragma unroll
        for (int r = 1; r < 8; r++) m = fmaxf(m, sc[b][r]);
#pragma unroll
        for (int off = 16; off; off >>= 1)
            m = fmaxf(m, __shfl_xor_sync(0xffffffffu, m, off));
        if (lane == 0) redm[(il * 8 + b) * 2 + jh] = m;
    }
    __syncthreads();
#pragma unroll
    for (int b = 0; b < 8; b++) {
        float m = fmaxf(redm[(il * 8 + b) * 2], redm[(il * 8 + b) * 2 + 1]);
        float ssum = 0.f;
#pragma unroll
        for (int r = 0; r < 8; r++) {
            float e = __expf(sc[b][r] - m);
            sc[b][r] = e;
            ssum += e;
        }
#pragma unroll
        for (int off = 16; off; off >>= 1)
            ssum += __shfl_xor_sync(0xffffffffu, ssum, off);
        if (lane == 0) reds[(il * 8 + b) * 2 + jh] = ssum;
    }
    __syncthreads();
#pragma unroll
    for (int b = 0; b < 8; b++) {
        float inv = 1.0f / (reds[(il * 8 + b) * 2] + reds[(il * 8 + b) * 2 + 1]);
        float* gp = g_P + (((size_t)(b * H_ + h) * S_) + i0 + il) * S_ + jh * 256 + lane;
#pragma unroll
        for (int r = 0; r < 8; r++)
            gp[r * 32] = sc[b][r] * inv;
    }
}

// ============================================================================
// av_kernel: per (b,h): Out[512x64] = P[512x512] @ V[512x64]
// 256x64 tile, TK=16, 256 threads (32x8), 8x8 micro.
// ============================================================================
#define APITCH 260
__global__ __launch_bounds__(256) void av_kernel()
{
    const int bh = blockIdx.y;
    const int i0 = blockIdx.x * 256;
    const float* P = g_P + (size_t)bh * S_ * S_;
    const float* V = g_V + (size_t)bh * S_ * D_;

    __shared__ float Xs[16][APITCH];
    __shared__ float Ws[16][68];

    const int tid = threadIdx.x;
    const int tx = tid & 7, ty = tid >> 3;           // 8 n-groups, 32 m-groups
    const int lr = tid >> 1, lc = (tid & 1) * 8;     // P loads rows lr, lr+128
    const int vr = tid >> 4, vc = (tid & 15) * 4;    // V loads

    const float* Prow0 = P + (size_t)(i0 + lr) * S_ + lc;
    const float* Prow1 = Prow0 + (size_t)128 * S_;
    const float* Vbase = V + (size_t)vr * D_ + vc;

    ull acc[8][4];
#pragma unroll
    for (int i = 0; i < 8; i++)
#pragma unroll
        for (int j = 0; j < 4; j++) acc[i][j] = 0ull;

    float4 p0a = *(const float4*)(Prow0);
    float4 p0b = *(const float4*)(Prow0 + 4);
    float4 p1a = *(const float4*)(Prow1);
    float4 p1b = *(const float4*)(Prow1 + 4);
    float4 vv  = *(const float4*)(Vbase);

    for (int k0 = 0; k0 < S_; k0 += 16) {
        Xs[lc + 0][lr] = p0a.x; Xs[lc + 1][lr] = p0a.y;
        Xs[lc + 2][lr] = p0a.z; Xs[lc + 3][lr] = p0a.w;
        Xs[lc + 4][lr] = p0b.x; Xs[lc + 5][lr] = p0b.y;
        Xs[lc + 6][lr] = p0b.z; Xs[lc + 7][lr] = p0b.w;
        Xs[lc + 0][lr + 128] = p1a.x; Xs[lc + 1][lr + 128] = p1a.y;
        Xs[lc + 2][lr + 128] = p1a.z; Xs[lc + 3][lr + 128] = p1a.w;
        Xs[lc + 4][lr + 128] = p1b.x; Xs[lc + 5][lr + 128] = p1b.y;
        Xs[lc + 6][lr + 128] = p1b.z; Xs[lc + 7][lr + 128] = p1b.w;
        *(float4*)&Ws[vr][vc] = vv;
        __syncthreads();
        if (k0 + 16 < S_) {
            p0a = *(const float4*)(Prow0 + k0 + 16);
            p0b = *(const float4*)(Prow0 + k0 + 20);
            p1a = *(const float4*)(Prow1 + k0 + 16);
            p1b = *(const float4*)(Prow1 + k0 + 20);
            vv  = *(const float4*)(Vbase + (size_t)(k0 + 16) * D_);
        }
#pragma unroll
        for (int kk = 0; kk < 16; kk++) MICRO_KK(Xs, Ws)
        __syncthreads();
    }

    UNPACK_C()

    const int b = bh >> 3, h = bh & 7;
#pragma unroll
    for (int i = 0; i < 8; i++) {
        int m = i0 + ty * 8 + i;
        float* row = g_AO + ((size_t)b * S_ + m) * E_ + h * 64 + tx * 8;
        float4 v0 = {c[i][0], c[i][1], c[i][2], c[i][3]};
        float4 v1 = {c[i][4], c[i][5], c[i][6], c[i][7]};
        *(float4*)row = v0;
        *(float4*)(row + 4) = v1;
    }
}

// ============================================================================
extern "C" void kernel_launch(void* const* d_in, const int* in_sizes, int n_in,
                              void* d_out, int out_size)
{
    const float* query = (const float*)d_in[0];
    const float* key   = (const float*)d_in[1];
    const float* value = (const float*)d_in[2];
    const unsigned char* mask = (const unsigned char*)d_in[3];
    const float* rel = (const float*)d_in[4];
    const float* Wq = (const float*)d_in[5];
    const float* bq = (const float*)d_in[6];
    const float* Wk = (const float*)d_in[7];
    const float* bk = (const float*)d_in[8];
    const float* Wv = (const float*)d_in[9];
    const float* bv = (const float*)d_in[10];
    const float* Wo = (const float*)d_in[11];
    const float* bo = (const float*)d_in[12];
    float* out = (float*)d_out;

    const int RS_SMEM = (2 * STG_F + 2048 + 128) * 4;
    cudaFuncSetAttribute(relsoftmax_kernel,
                         cudaFuncAttributeMaxDynamicSharedMemorySize, RS_SMEM);

    dim3 gproj(32, 4);   // 4096/128, 512/128
    proj_kernel<<<gproj, 256>>>(query, Wq, bq, 1.0f,   0, 0, nullptr);
    proj_kernel<<<gproj, 256>>>(key,   Wk, bk, 0.125f, 0, 1, nullptr);
    proj_kernel<<<gproj, 256>>>(value, Wv, bv, 1.0f,   0, 2, nullptr);

    qk_kernel<<<dim3(4, 4, 64), 256>>>();

    relsoftmax_kernel<<<dim3(S_ / 4, H_), 256, RS_SMEM>>>(mask, rel);

    av_kernel<<<dim3(2, 64), 256>>>();

    proj_kernel<<<gproj, 256>>>(nullptr, Wo, bo, 1.0f, 1, 3, out);
}

// round 12
// speedup vs baseline: 6.7584x; 1.3170x over previous
#include <cuda_runtime.h>
#include <cuda_bf16.h>
#include <cstdint>

#define B_ 8
#define H_ 8
#define S_ 512
#define D_ 64
#define E_ 512

typedef unsigned long long ull;

// ---- packed f32x2 helpers (SIMT kernels) ----
__device__ __forceinline__ ull pack_dup(float a) {
    ull r; asm("mov.b64 %0, {%1, %1};" : "=l"(r) : "f"(a)); return r;
}
__device__ __forceinline__ ull pack2(float x, float y) {
    ull r; asm("mov.b64 %0, {%1, %2};" : "=l"(r) : "f"(x), "f"(y)); return r;
}
__device__ __forceinline__ ull ffma2(ull a, ull b, ull c) {
    ull d; asm("fma.rn.f32x2 %0, %1, %2, %3;" : "=l"(d) : "l"(a), "l"(b), "l"(c)); return d;
}
__device__ __forceinline__ float2 unpack2(ull u) {
    float lo, hi; asm("mov.b64 {%0, %1}, %2;" : "=f"(lo), "=f"(hi) : "l"(u));
    float2 f; f.x = lo; f.y = hi; return f;
}
__device__ __forceinline__ void cp_async16(void* dst, const void* src) {
    uint32_t s = (uint32_t)__cvta_generic_to_shared(dst);
    asm volatile("cp.async.cg.shared.global [%0], [%1], 16;" :: "r"(s), "l"(src));
}
#define CP_COMMIT() asm volatile("cp.async.commit_group;")

__device__ __forceinline__ uint32_t smem_u32(const void* p) {
    return (uint32_t)__cvta_generic_to_shared(p);
}

// ---- mma.sync helpers (non-'a'-gated: valid on plain sm_103) ----
#define LDSM_X4(r0, r1, r2, r3, addr)                                         \
    asm volatile("ldmatrix.sync.aligned.m8n8.x4.shared.b16 {%0,%1,%2,%3}, [%4];" \
                 : "=r"(r0), "=r"(r1), "=r"(r2), "=r"(r3) : "r"(addr))

__device__ __forceinline__ void mma16816(float* d, const uint32_t* a, const uint32_t* b) {
    asm volatile(
        "mma.sync.aligned.m16n8k16.row.col.f32.bf16.bf16.f32 "
        "{%0,%1,%2,%3}, {%4,%5,%6,%7}, {%8,%9}, {%0,%1,%2,%3};"
        : "+f"(d[0]), "+f"(d[1]), "+f"(d[2]), "+f"(d[3])
        : "r"(a[0]), "r"(a[1]), "r"(a[2]), "r"(a[3]), "r"(b[0]), "r"(b[1]));
}

// ---- scratch ----
__device__ float g_Q [B_ * H_ * S_ * D_];
__device__ float g_Kt[B_ * H_ * D_ * S_];            // [b][h][d][s], pre-scaled 1/8
__device__ float g_V [B_ * H_ * S_ * D_];
__device__ float g_P [(size_t)B_ * H_ * S_ * S_];
__device__ float g_AO[B_ * S_ * E_];

// ============================================================================
// proj_mma: Y = X @ W^T + bias via mma.sync bf16 3-term split.
// M=4096, N=512, K=512. CTA tile 128x128, 8 warps (4m x 2n), warp 32x64.
// BK=32, double-buffered smem; fp32->bf16 hi/lo split inline on load.
// out_sel 0: g_Q   1: g_Kt (d-major, scaled)   2: g_V   3: Oext
// ============================================================================
#define PROW 80                     // smem bytes per row (64 data + 16 pad)
#define TILE_B (128 * PROW)         // 10240 B per bf16 tile
#define STAGE_B (4 * TILE_B)        // Ahi,Alo,Bhi,Blo per stage = 40960 B
#define PROJ_SMEM (2 * STAGE_B)     // 81920 B

__device__ __forceinline__ void split_sts(char* smem, uint32_t hi_off, uint32_t lo_off,
                                          const float* f /*16 vals*/)
{
#pragma unroll
    for (int c = 0; c < 2; c++) {
        uint32_t h[4], l[4];
#pragma unroll
        for (int i = 0; i < 4; i++) {
            float x = f[c * 8 + i * 2], y = f[c * 8 + i * 2 + 1];
            __nv_bfloat162 hb = __floats2bfloat162_rn(x, y);
            h[i] = *(uint32_t*)&hb;
            __nv_bfloat162 lb = __floats2bfloat162_rn(x - __low2float(hb),
                                                      y - __high2float(hb));
            l[i] = *(uint32_t*)&lb;
        }
        *(uint4*)(smem + hi_off + c * 16) = make_uint4(h[0], h[1], h[2], h[3]);
        *(uint4*)(smem + lo_off + c * 16) = make_uint4(l[0], l[1], l[2], l[3]);
    }
}

__global__ __launch_bounds__(256, 1) void proj_mma(
    const float* __restrict__ Xext, const float* __restrict__ W,
    const float* __restrict__ bias, float scale,
    int in_sel, int out_sel, float* __restrict__ Oext)
{
    extern __shared__ char smc[];
    const float* X = in_sel ? g_AO : Xext;

    const int tid = threadIdx.x;
    const int wid = tid >> 5;
    const int lane = tid & 31;
    const int warp_m = wid >> 1;        // 0..3
    const int warp_n = wid & 1;         // 0..1
    const int m0 = blockIdx.x * 128;
    const int n0 = blockIdx.y * 128;

    const uint32_t smb = smem_u32(smc);

    // ldmatrix per-lane address components
    const uint32_t aoff = (warp_m * 32 + (lane & 15)) * PROW + (lane >> 4) * 16;
    const uint32_t boff = (warp_n * 64 + ((lane >> 4) & 1) * 8 + (lane & 7)) * PROW
                        + ((lane >> 3) & 1) * 16;

    // gmem->smem staging assignment
    const int row = tid >> 1, half = tid & 1;
    const float* Ap = X + (size_t)(m0 + row) * E_ + half * 16;
    const float* Bp = W + (size_t)(n0 + row) * E_ + half * 16;
    const uint32_t sts_off = row * PROW + half * 32;

    float acc[2][8][4];
#pragma unroll
    for (int mt = 0; mt < 2; mt++)
#pragma unroll
        for (int nt = 0; nt < 8; nt++)
#pragma unroll
            for (int i = 0; i < 4; i++) acc[mt][nt][i] = 0.f;

    float ar[16], br[16];
#pragma unroll
    for (int i = 0; i < 4; i++) {
        *(float4*)&ar[i * 4] = *(const float4*)(Ap + i * 4);
        *(float4*)&br[i * 4] = *(const float4*)(Bp + i * 4);
    }
    split_sts(smc, 0 * TILE_B + sts_off, 1 * TILE_B + sts_off, ar);
    split_sts(smc, 2 * TILE_B + sts_off, 3 * TILE_B + sts_off, br);
    __syncthreads();

#pragma unroll 1
    for (int s = 0; s < 16; s++) {
        const uint32_t st = smb + (s & 1) * STAGE_B;
        if (s < 15) {
            const float* Ap2 = Ap + (s + 1) * 32;
            const float* Bp2 = Bp + (s + 1) * 32;
#pragma unroll
            for (int i = 0; i < 4; i++) {
                *(float4*)&ar[i * 4] = *(const float4*)(Ap2 + i * 4);
                *(float4*)&br[i * 4] = *(const float4*)(Bp2 + i * 4);
            }
        }

#pragma unroll
        for (int ks = 0; ks < 2; ks++) {
            uint32_t ahi[2][4], alo[2][4];
#pragma unroll
            for (int mt = 0; mt < 2; mt++) {
                uint32_t ao = st + aoff + mt * (16 * PROW) + ks * 32;
                LDSM_X4(ahi[mt][0], ahi[mt][1], ahi[mt][2], ahi[mt][3], ao);
                LDSM_X4(alo[mt][0], alo[mt][1], alo[mt][2], alo[mt][3], ao + TILE_B);
            }
#pragma unroll
            for (int np = 0; np < 4; np++) {
                uint32_t bo = st + 2 * TILE_B + boff + np * (16 * PROW) + ks * 32;
                uint32_t bhi[4], blo[4];
                LDSM_X4(bhi[0], bhi[1], bhi[2], bhi[3], bo);
                LDSM_X4(blo[0], blo[1], blo[2], blo[3], bo + TILE_B);
#pragma unroll
                for (int mt = 0; mt < 2; mt++)
#pragma unroll
                    for (int n2 = 0; n2 < 2; n2++) {
                        float* d = acc[mt][np * 2 + n2];
                        mma16816(d, ahi[mt], &bhi[n2 * 2]);
                        mma16816(d, ahi[mt], &blo[n2 * 2]);
                        mma16816(d, alo[mt], &bhi[n2 * 2]);
                    }
            }
        }

        if (s < 15) {
            char* nstage = smc + ((s + 1) & 1) * STAGE_B;
            split_sts(nstage, 0 * TILE_B + sts_off, 1 * TILE_B + sts_off, ar);
            split_sts(nstage, 2 * TILE_B + sts_off, 3 * TILE_B + sts_off, br);
        }
        __syncthreads();
    }

    // ---- epilogue ----
#pragma unroll
    for (int mt = 0; mt < 2; mt++) {
        const int r0 = m0 + warp_m * 32 + mt * 16 + (lane >> 2);
        const int r1 = r0 + 8;
#pragma unroll
        for (int nt = 0; nt < 8; nt++) {
            const int n = n0 + warp_n * 64 + nt * 8 + (lane & 3) * 2;
            float2 bv = *(const float2*)&bias[n];
            float v00 = acc[mt][nt][0] + bv.x, v01 = acc[mt][nt][1] + bv.y;
            float v10 = acc[mt][nt][2] + bv.x, v11 = acc[mt][nt][3] + bv.y;

            if (out_sel == 3) {
                *(float2*)&Oext[(size_t)r0 * E_ + n] = make_float2(v00, v01);
                *(float2*)&Oext[(size_t)r1 * E_ + n] = make_float2(v10, v11);
            } else if (out_sel == 1) {
                const int hh = n >> 6, dd = n & 63;
                {
                    const int bb = r0 >> 9, srow = r0 & (S_ - 1);
                    float* base = g_Kt + ((size_t)(bb * H_ + hh) * D_) * S_ + srow;
                    base[(size_t)dd * S_]       = v00 * scale;
                    base[(size_t)(dd + 1) * S_] = v01 * scale;
                }
                {
                    const int bb = r1 >> 9, srow = r1 & (S_ - 1);
                    float* base = g_Kt + ((size_t)(bb * H_ + hh) * D_) * S_ + srow;
                    base[(size_t)dd * S_]       = v10 * scale;
                    base[(size_t)(dd + 1) * S_] = v11 * scale;
                }
            } else {
                float* dst = (out_sel == 0) ? g_Q : g_V;
                const int hh = n >> 6, dd = n & 63;
                {
                    const int bb = r0 >> 9, srow = r0 & (S_ - 1);
                    *(float2*)&dst[(((size_t)(bb * H_ + hh) * S_) + srow) * D_ + dd] =
                        make_float2(v00, v01);
                }
                {
                    const int bb = r1 >> 9, srow = r1 & (S_ - 1);
                    *(float2*)&dst[(((size_t)(bb * H_ + hh) * S_) + srow) * D_ + dd] =
                        make_float2(v10, v11);
                }
            }
        }
    }
}

#define PITCH 132

#define MICRO_KK(XS, WS)                                                    \
    {                                                                       \
        float4 a0 = *(const float4*)&XS[kk][ty * 8];                        \
        float4 a1 = *(const float4*)&XS[kk][ty * 8 + 4];                    \
        float4 b0 = *(const float4*)&WS[kk][tx * 8];                        \
        float4 b1 = *(const float4*)&WS[kk][tx * 8 + 4];                    \
        ull bp0 = pack2(b0.x, b0.y), bp1 = pack2(b0.z, b0.w);               \
        ull bp2 = pack2(b1.x, b1.y), bp3 = pack2(b1.z, b1.w);               \
        float av_[8] = {a0.x, a0.y, a0.z, a0.w, a1.x, a1.y, a1.z, a1.w};    \
        _Pragma("unroll")                                                   \
        for (int i = 0; i < 8; i++) {                                       \
            ull ad = pack_dup(av_[i]);                                      \
            acc[i][0] = ffma2(ad, bp0, acc[i][0]);                          \
            acc[i][1] = ffma2(ad, bp1, acc[i][1]);                          \
            acc[i][2] = ffma2(ad, bp2, acc[i][2]);                          \
            acc[i][3] = ffma2(ad, bp3, acc[i][3]);                          \
        }                                                                   \
    }

#define UNPACK_C()                                                          \
    float c[8][8];                                                          \
    _Pragma("unroll")                                                       \
    for (int i = 0; i < 8; i++)                                             \
        _Pragma("unroll")                                                   \
        for (int jp = 0; jp < 4; jp++) {                                    \
            float2 f = unpack2(acc[i][jp]);                                 \
            c[i][jp * 2] = f.x; c[i][jp * 2 + 1] = f.y;                     \
        }

// ============================================================================
// qk_kernel: P = Q @ Kt per (b,h), 128x128 tile, 8x8 micro (proven R8 version)
// ============================================================================
__global__ __launch_bounds__(256, 2) void qk_kernel()
{
    const int bh = blockIdx.z;
    const int i0 = blockIdx.x * 128;
    const int j0 = blockIdx.y * 128;
    const float* Q  = g_Q  + (size_t)bh * S_ * D_;
    const float* Kt = g_Kt + (size_t)bh * D_ * S_;

    __shared__ float Xs[16][PITCH];
    __shared__ float Ws[16][PITCH];

    const int tid = threadIdx.x;
    const int tx = tid & 15, ty = tid >> 4;
    const int lr = tid >> 1, lc = (tid & 1) * 8;
    const int kr = tid >> 4, kc = (tid & 15) * 8;

    const float* Qrow  = Q + (size_t)(i0 + lr) * D_ + lc;
    const float* Ktrow = Kt + (size_t)kr * S_ + j0 + kc;

    ull acc[8][4];
#pragma unroll
    for (int i = 0; i < 8; i++)
#pragma unroll
        for (int j = 0; j < 4; j++) acc[i][j] = 0ull;

    float4 x0 = *(const float4*)(Qrow);
    float4 x1 = *(const float4*)(Qrow + 4);
    float4 w0 = *(const float4*)(Ktrow);
    float4 w1 = *(const float4*)(Ktrow + 4);

    for (int k0 = 0; k0 < D_; k0 += 16) {
        Xs[lc + 0][lr] = x0.x; Xs[lc + 1][lr] = x0.y;
        Xs[lc + 2][lr] = x0.z; Xs[lc + 3][lr] = x0.w;
        Xs[lc + 4][lr] = x1.x; Xs[lc + 5][lr] = x1.y;
        Xs[lc + 6][lr] = x1.z; Xs[lc + 7][lr] = x1.w;
        *(float4*)&Ws[kr][kc]     = w0;
        *(float4*)&Ws[kr][kc + 4] = w1;
        __syncthreads();
        if (k0 + 16 < D_) {
            x0 = *(const float4*)(Qrow + k0 + 16);
            x1 = *(const float4*)(Qrow + k0 + 20);
            w0 = *(const float4*)(Ktrow + (size_t)(k0 + 16) * S_);
            w1 = *(const float4*)(Ktrow + (size_t)(k0 + 16) * S_ + 4);
        }
#pragma unroll
        for (int kk = 0; kk < 16; kk++) MICRO_KK(Xs, Ws)
        __syncthreads();
    }

    UNPACK_C()

    float* Pout = g_P + (size_t)bh * S_ * S_;
#pragma unroll
    for (int i = 0; i < 8; i++) {
        int m = i0 + ty * 8 + i;
        float4 v0 = {c[i][0], c[i][1], c[i][2], c[i][3]};
        float4 v1 = {c[i][4], c[i][5], c[i][6], c[i][7]};
        *(float4*)&Pout[(size_t)m * S_ + j0 + tx * 8]     = v0;
        *(float4*)&Pout[(size_t)m * S_ + j0 + tx * 8 + 4] = v1;
    }
}

// ============================================================================
// relsoftmax_kernel (proven R8 version)
// ============================================================================
#define ROWF 68
#define STG_F (4 * 2 * 32 * ROWF)

__global__ __launch_bounds__(256, 1) void relsoftmax_kernel(
    const unsigned char* __restrict__ mask,
    const float* __restrict__ rel)
{
    extern __shared__ float sm[];
    float* stg0 = sm;
    float* stg1 = sm + STG_F;
    ull*   q_s  = (ull*)(sm + 2 * STG_F);
    float* redm = sm + 2 * STG_F + 2048;
    float* reds = redm + 64;

    const int h  = blockIdx.y;
    const int i0 = blockIdx.x * 4;
    const int tid  = threadIdx.x;
    const int w    = tid >> 5;
    const int lane = tid & 31;
    const int il = w >> 1;
    const int jh = w & 1;

    for (int t = tid; t < 1024; t += 256) {
        int d2 = t & 31, b = (t >> 5) & 7, ii = t >> 8;
        q_s[t] = *(const ull*)&g_Q[(((size_t)(b * H_ + h) * S_) + i0 + ii) * D_ + d2 * 2];
    }

    ull acc[8][8];
#pragma unroll
    for (int b = 0; b < 8; b++)
#pragma unroll
        for (int r = 0; r < 8; r++) acc[b][r] = 0ull;

    auto load_round = [&](int r, float* buf) {
#pragma unroll
        for (int t = 0; t < 16; t++) {
            int f = tid + t * 256;
            int d4 = f & 15, jj = (f >> 4) & 31, jhh = (f >> 9) & 1, ii = f >> 10;
            int j = jhh * 256 + r * 32 + jj;
            const float* src = rel +
                ((((size_t)(i0 + ii) * S_ + j) * H_) + h) * D_ + d4 * 4;
            float* dst = buf + ((size_t)((ii * 2 + jhh) * 32 + jj)) * ROWF + d4 * 4;
            cp_async16(dst, src);
        }
        CP_COMMIT();
    };

    load_round(0, stg0);
#pragma unroll
    for (int r = 0; r < 8; r++) {
        float* curbuf = (r & 1) ? stg1 : stg0;
        if (r < 7) {
            load_round(r + 1, (r & 1) ? stg0 : stg1);
            asm volatile("cp.async.wait_group 1;");
        } else {
            asm volatile("cp.async.wait_group 0;");
        }
        __syncthreads();
        const float* relrow = curbuf + ((size_t)((il * 2 + jh) * 32 + lane)) * ROWF;
        const ull* qrow = q_s + il * 256;
#pragma unroll 4
        for (int d2 = 0; d2 < 32; d2++) {
            ull r2 = *(const ull*)(relrow + d2 * 2);
#pragma unroll
            for (int b = 0; b < 8; b++)
                acc[b][r] = ffma2(qrow[b * 32 + d2], r2, acc[b][r]);
        }
        __syncthreads();
    }

    float sc[8][8];
#pragma unroll
    for (int b = 0; b < 8; b++) {
        const float* gp = g_P + (((size_t)(b * H_ + h) * S_) + i0 + il) * S_ + jh * 256 + lane;
        const unsigned char* mrow = mask + (size_t)b * S_ + jh * 256 + lane;
#pragma unroll
        for (int r = 0; r < 8; r++) {
            float2 f = unpack2(acc[b][r]);
            float s = f.x + f.y + gp[r * 32];
            if (mrow[r * 32]) s = -1e9f;
            sc[b][r] = s;
        }
    }

#pragma unroll
    for (int b = 0; b < 8; b++) {
        float m = sc[b][0];
#pragma unroll
        for (int r = 1; r < 8; r++) m = fmaxf(m, sc[b][r]);
#pragma unroll
        for (int off = 16; off; off >>= 1)
            m = fmaxf(m, __shfl_xor_sync(0xffffffffu, m, off));
        if (lane == 0) redm[(il * 8 + b) * 2 + jh] = m;
    }
    __syncthreads();
#pragma unroll
    for (int b = 0; b < 8; b++) {
        float m = fmaxf(redm[(il * 8 + b) * 2], redm[(il * 8 + b) * 2 + 1]);
        float ssum = 0.f;
#pragma unroll
        for (int r = 0; r < 8; r++) {
            float e = __expf(sc[b][r] - m);
            sc[b][r] = e;
            ssum += e;
        }
#pragma unroll
        for (int off = 16; off; off >>= 1)
            ssum += __shfl_xor_sync(0xffffffffu, ssum, off);
        if (lane == 0) reds[(il * 8 + b) * 2 + jh] = ssum;
    }
    __syncthreads();
#pragma unroll
    for (int b = 0; b < 8; b++) {
        float inv = 1.0f / (reds[(il * 8 + b) * 2] + reds[(il * 8 + b) * 2 + 1]);
        float* gp = g_P + (((size_t)(b * H_ + h) * S_) + i0 + il) * S_ + jh * 256 + lane;
#pragma unroll
        for (int r = 0; r < 8; r++)
            gp[r * 32] = sc[b][r] * inv;
    }
}

// ============================================================================
// av_kernel (proven R8 version): Out = P @ V per (b,h), 256x64 tile
// ============================================================================
#define APITCH 260
__global__ __launch_bounds__(256) void av_kernel()
{
    const int bh = blockIdx.y;
    const int i0 = blockIdx.x * 256;
    const float* P = g_P + (size_t)bh * S_ * S_;
    const float* V = g_V + (size_t)bh * S_ * D_;

    __shared__ float Xs[16][APITCH];
    __shared__ float Ws[16][68];

    const int tid = threadIdx.x;
    const int tx = tid & 7, ty = tid >> 3;
    const int lr = tid >> 1, lc = (tid & 1) * 8;
    const int vr = tid >> 4, vc = (tid & 15) * 4;

    const float* Prow0 = P + (size_t)(i0 + lr) * S_ + lc;
    const float* Prow1 = Prow0 + (size_t)128 * S_;
    const float* Vbase = V + (size_t)vr * D_ + vc;

    ull acc[8][4];
#pragma unroll
    for (int i = 0; i < 8; i++)
#pragma unroll
        for (int j = 0; j < 4; j++) acc[i][j] = 0ull;

    float4 p0a = *(const float4*)(Prow0);
    float4 p0b = *(const float4*)(Prow0 + 4);
    float4 p1a = *(const float4*)(Prow1);
    float4 p1b = *(const float4*)(Prow1 + 4);
    float4 vv  = *(const float4*)(Vbase);

    for (int k0 = 0; k0 < S_; k0 += 16) {
        Xs[lc + 0][lr] = p0a.x; Xs[lc + 1][lr] = p0a.y;
        Xs[lc + 2][lr] = p0a.z; Xs[lc + 3][lr] = p0a.w;
        Xs[lc + 4][lr] = p0b.x; Xs[lc + 5][lr] = p0b.y;
        Xs[lc + 6][lr] = p0b.z; Xs[lc + 7][lr] = p0b.w;
        Xs[lc + 0][lr + 128] = p1a.x; Xs[lc + 1][lr + 128] = p1a.y;
        Xs[lc + 2][lr + 128] = p1a.z; Xs[lc + 3][lr + 128] = p1a.w;
        Xs[lc + 4][lr + 128] = p1b.x; Xs[lc + 5][lr + 128] = p1b.y;
        Xs[lc + 6][lr + 128] = p1b.z; Xs[lc + 7][lr + 128] = p1b.w;
        *(float4*)&Ws[vr][vc] = vv;
        __syncthreads();
        if (k0 + 16 < S_) {
            p0a = *(const float4*)(Prow0 + k0 + 16);
            p0b = *(const float4*)(Prow0 + k0 + 20);
            p1a = *(const float4*)(Prow1 + k0 + 16);
            p1b = *(const float4*)(Prow1 + k0 + 20);
            vv  = *(const float4*)(Vbase + (size_t)(k0 + 16) * D_);
        }
#pragma unroll
        for (int kk = 0; kk < 16; kk++) MICRO_KK(Xs, Ws)
        __syncthreads();
    }

    UNPACK_C()

    const int b = bh >> 3, h = bh & 7;
#pragma unroll
    for (int i = 0; i < 8; i++) {
        int m = i0 + ty * 8 + i;
        float* row = g_AO + ((size_t)b * S_ + m) * E_ + h * 64 + tx * 8;
        float4 v0 = {c[i][0], c[i][1], c[i][2], c[i][3]};
        float4 v1 = {c[i][4], c[i][5], c[i][6], c[i][7]};
        *(float4*)row = v0;
        *(float4*)(row + 4) = v1;
    }
}

// ============================================================================
extern "C" void kernel_launch(void* const* d_in, const int* in_sizes, int n_in,
                              void* d_out, int out_size)
{
    const float* query = (const float*)d_in[0];
    const float* key   = (const float*)d_in[1];
    const float* value = (const float*)d_in[2];
    const unsigned char* mask = (const unsigned char*)d_in[3];
    const float* rel = (const float*)d_in[4];
    const float* Wq = (const float*)d_in[5];
    const float* bq = (const float*)d_in[6];
    const float* Wk = (const float*)d_in[7];
    const float* bk = (const float*)d_in[8];
    const float* Wv = (const float*)d_in[9];
    const float* bv = (const float*)d_in[10];
    const float* Wo = (const float*)d_in[11];
    const float* bo = (const float*)d_in[12];
    float* out = (float*)d_out;

    static bool attrs_set = false;
    if (!attrs_set) {
        cudaFuncSetAttribute(relsoftmax_kernel,
                             cudaFuncAttributeMaxDynamicSharedMemorySize,
                             (2 * STG_F + 2048 + 128) * 4);
        cudaFuncSetAttribute(proj_mma,
                             cudaFuncAttributeMaxDynamicSharedMemorySize, PROJ_SMEM);
        attrs_set = true;
    }
    const int RS_SMEM = (2 * STG_F + 2048 + 128) * 4;

    dim3 gproj(32, 4);   // 4096/128 m-tiles, 512/128 n-tiles
    proj_mma<<<gproj, 256, PROJ_SMEM>>>(query, Wq, bq, 1.0f,   0, 0, nullptr);
    proj_mma<<<gproj, 256, PROJ_SMEM>>>(key,   Wk, bk, 0.125f, 0, 1, nullptr);
    proj_mma<<<gproj, 256, PROJ_SMEM>>>(value, Wv, bv, 1.0f,   0, 2, nullptr);

    qk_kernel<<<dim3(4, 4, 64), 256>>>();

    relsoftmax_kernel<<<dim3(S_ / 4, H_), 256, RS_SMEM>>>(mask, rel);

    av_kernel<<<dim3(2, 64), 256>>>();

    proj_mma<<<gproj, 256, PROJ_SMEM>>>(nullptr, Wo, bo, 1.0f, 1, 3, out);
}